// round 7
// baseline (speedup 1.0000x reference)
#include <cuda_runtime.h>
#include <cstdint>

#define B   32
#define H   384
#define W   640
#define C   128
#define HS  96      // H / SCALE
#define WS  160     // W / SCALE
#define FW  30
#define THRESH 0.015f
#define TOPK 2000
#define PIX 32         // pixels per thread per select swath (32K px per swath)

// Static device scratch (allocation-free rule: __device__ globals allowed)
__device__ float d_hwc[(size_t)B * HS * WS * C];   // full transposed featmap
__device__ int   d_idx[B * TOPK];                  // ascending selected linear indices, -1 = invalid

// ---------------------------------------------------------------------------
// Fused kernel 1: block-specialized.
//   blocks [0, B)            : ordered selection, one batch each.
//   blocks [B, B + TT)       : CHW -> HWC transpose of the FULL featmap
//                              (independent of selection -> runs concurrently).
// Block = 1024 threads.
//
// Selection: the in-region row-major pixel stream is scanned in swaths of
// 1024*PIX = 32768 pixels. Every thread owns PIX consecutive pixels; all its
// loads are independent (single DRAM roundtrip per swath). One block scan of
// per-thread popcounts assigns ordered global ranks. At ~98.5% density the
// first swath covers TOPK, so the loop body runs once.
//
// Transpose: task t -> (b, y, xt); each block moves a 32(x) x 128(c) slab
// through smem (4 x 32x32 tiles), fully coalesced on both sides.
// ---------------------------------------------------------------------------
#define TT (B * HS * (WS / 32))     // 15360 transpose tasks

__global__ __launch_bounds__(1024) void fused_kernel(
    const float* __restrict__ prob,
    const float* __restrict__ feat,
    const float* __restrict__ ratio,
    const int* __restrict__ rshape_raw,
    float* __restrict__ pts_out)
{
    __shared__ float smem[4 * 32 * 33];   // transpose tiles / (select uses first ints)

    if (blockIdx.x >= B) {
        // ---------------- transpose path ----------------
        const int t = blockIdx.x - B;
        const int b  = t / (HS * 5);
        const int rm = t - b * (HS * 5);
        const int y  = rm / 5;
        const int xt = rm - y * 5;

        const int tx = threadIdx.x & 31;        // x within tile
        const int cr = threadIdx.x >> 5;        // channel row 0..31

        float* tile = smem;                      // [4][32][33]
        const float* src = feat + ((size_t)b * C) * (HS * WS) + (size_t)y * WS + xt * 32;
        #pragma unroll
        for (int i = 0; i < 4; ++i) {
            const int cc = i * 32 + cr;
            tile[(i * 32 + cr) * 33 + tx] = src[(size_t)cc * (HS * WS) + tx];
        }
        __syncthreads();
        // store: thread -> (x = tid>>5, c = i*32 + (tid&31)), contiguous in c
        const int co = threadIdx.x & 31;
        const int xr = threadIdx.x >> 5;
        float* dst = d_hwc + ((size_t)(b * HS + y) * WS + xt * 32 + xr) * C;
        #pragma unroll
        for (int i = 0; i < 4; ++i) {
            dst[i * 32 + co] = tile[(i * 32 + co) * 33 + xr];
        }
        return;
    }

    // ---------------- selection path ----------------
    const int b    = blockIdx.x;
    const int tid  = threadIdx.x;
    const int warp = tid >> 5;
    const int lane = tid & 31;

    int* sWarpBase = (int*)smem;        // [32]
    int* sTotal    = (int*)smem + 32;

    // r_shape dtype sniff: int64 LE -> word 1 is high half of first value (0);
    // int32 -> word 1 is W != 0.
    const int stride = (rshape_raw[1] == 0) ? 2 : 1;
    const int r0 = rshape_raw[(2 * b)     * stride];
    const int r1 = rshape_raw[(2 * b + 1) * stride];
    const int rowW     = r1 - 2 * FW;              // valid cols per row
    const int totalPix = (r0 - 2 * FW) * rowW;     // in-region pixel count
    const float rv = ratio[b];
    const float* pb = prob + (size_t)b * H * W;

    int base = 0;
    for (int sw = 0; sw < totalPix && base < TOPK; sw += 1024 * PIX) {
        const int pix0 = sw + PIX * tid;
        unsigned pmask = 0;
        int ri0 = 0, ci0 = 0;
        if (rowW > 0 && pix0 < totalPix) {
            const int rq = pix0 / rowW;
            ri0 = FW + rq;
            ci0 = FW + pix0 - rq * rowW;
            int ri = ri0, ci = ci0;
            #pragma unroll
            for (int j = 0; j < PIX; ++j) {
                if ((pix0 + j) < totalPix && pb[(size_t)ri * W + ci] > THRESH)
                    pmask |= (1u << j);
                if (++ci >= FW + rowW) { ci = FW; ++ri; }
            }
        }
        const int cnt = __popc(pmask);

        // block exclusive scan of per-thread cnt
        int incl = cnt;
        #pragma unroll
        for (int d = 1; d < 32; d <<= 1) {
            int y2 = __shfl_up_sync(0xffffffffu, incl, d);
            if (lane >= d) incl += y2;
        }
        if (lane == 31) sWarpBase[warp] = incl;
        __syncthreads();
        if (tid < 32) {
            int v = sWarpBase[tid];
            int x = v;
            #pragma unroll
            for (int d = 1; d < 32; d <<= 1) {
                int y2 = __shfl_up_sync(0xffffffffu, x, d);
                if (tid >= d) x += y2;
            }
            sWarpBase[tid] = x - v;
            if (tid == 31) *sTotal = x;
        }
        __syncthreads();
        int pos = base + sWarpBase[warp] + (incl - cnt);

        if (pmask && pos < TOPK) {
            int ri = ri0, ci = ci0;
            #pragma unroll
            for (int j = 0; j < PIX; ++j) {
                if ((pmask >> j) & 1u) {
                    if (pos < TOPK) {
                        d_idx[b * TOPK + pos] = ri * W + ci;
                        ((float2*)pts_out)[(size_t)b * TOPK + pos] =
                            make_float2((float)ci / rv, (float)ri / rv);
                    }
                    ++pos;
                }
                if (++ci >= FW + rowW) { ci = FW; ++ri; }
            }
        }
        const int total = *sTotal;
        __syncthreads();           // protect smem for next iteration
        base += total;
    }

    // fill invalid tail
    const int cnt = (base < TOPK) ? base : TOPK;
    for (int k = cnt + tid; k < TOPK; k += 1024) {
        d_idx[b * TOPK + k] = -1;
        ((float2*)pts_out)[(size_t)b * TOPK + k] = make_float2(0.0f, 0.0f);
    }
}

// ---------------------------------------------------------------------------
// Kernel 2: bilinear gather with shared point-decode.
// 256 threads = 8 point-lanes x 32 channel-groups; 32 points per block.
// Threads 0..31 decode each point ONCE (tap base offset in float4 units +
// weight vector) into smem; main loop is LDS + 4x LDG.128 + FFMA + STG.128.
// ---------------------------------------------------------------------------
__global__ __launch_bounds__(256) void gather_kernel(float* __restrict__ des_out)
{
    const int b  = blockIdx.y;
    const int p0 = blockIdx.x * 32;
    const int cg = threadIdx.x & 31;   // channel group (4 ch each)
    const int pl = threadIdx.x >> 5;   // point lane 0..7

    __shared__ int    sOff[32];
    __shared__ float4 sWt[32];
    if (threadIdx.x < 32) {
        const int p = p0 + threadIdx.x;
        const int lin = (p < TOPK) ? d_idx[b * TOPK + p] : -1;
        int off = -1;
        float4 wt = make_float4(0.f, 0.f, 0.f, 0.f);
        if (lin >= 0) {
            const int y = lin / W;
            const int x = lin - y * W;
            const int x0 = x >> 2;
            const int y0 = y >> 2;
            const float fx = (float)(x & 3) * 0.25f;
            const float fy = (float)(y & 3) * 0.25f;
            off = ((b * HS + y0) * WS + x0) * (C / 4);
            wt = make_float4((1.f - fx) * (1.f - fy),   // Ia (y0,x0)
                             (1.f - fx) * fy,           // Ib (y1,x0)
                             fx * (1.f - fy),           // Ic (y0,x1)
                             fx * fy);                  // Id (y1,x1)
        }
        sOff[threadIdx.x] = off;
        sWt[threadIdx.x]  = wt;
    }
    __syncthreads();

    const float4* hwc4 = (const float4*)d_hwc;
    #pragma unroll
    for (int i = 0; i < 4; ++i) {
        const int j = pl + i * 8;
        const int p = p0 + j;
        if (p < TOPK) {
            const int off = sOff[j];
            float4 v = make_float4(0.f, 0.f, 0.f, 0.f);
            if (off >= 0) {
                const float4 w = sWt[j];
                const float4* basep = hwc4 + off + cg;
                const float4 Ia = basep[0];                   // (y0,x0)
                const float4 Ic = basep[C / 4];               // (y0,x1)
                const float4 Ib = basep[WS * (C / 4)];        // (y1,x0)
                const float4 Id = basep[WS * (C / 4) + C / 4];// (y1,x1)
                v.x = Ia.x * w.x + Ib.x * w.y + Ic.x * w.z + Id.x * w.w;
                v.y = Ia.y * w.x + Ib.y * w.y + Ic.y * w.z + Id.y * w.w;
                v.z = Ia.z * w.x + Ib.z * w.y + Ic.z * w.z + Id.z * w.w;
                v.w = Ia.w * w.x + Ib.w * w.y + Ic.w * w.z + Id.w * w.w;
            }
            ((float4*)des_out)[((size_t)b * TOPK + p) * (C / 4) + cg] = v;
        }
    }
}

// ---------------------------------------------------------------------------
extern "C" void kernel_launch(void* const* d_in, const int* in_sizes, int n_in,
                              void* d_out, int out_size)
{
    const float* prob   = (const float*)d_in[0];      // [B,1,H,W]
    const float* feat   = (const float*)d_in[1];      // [B,C,HS,WS]
    const float* ratio  = (const float*)d_in[2];      // [B,1]
    const int*   rshape = (const int*)d_in[3];        // [B,2] int32 (or int64-packed)

    float* pts_out = (float*)d_out;                        // [B,TOPK,2]
    float* des_out = (float*)d_out + (size_t)B * TOPK * 2; // [B,TOPK,C]

    fused_kernel<<<B + TT, 1024>>>(prob, feat, ratio, rshape, pts_out);
    gather_kernel<<<dim3((TOPK + 31) / 32, B), 256>>>(des_out);
}

// round 8
// speedup vs baseline: 4.0143x; 4.0143x over previous
#include <cuda_runtime.h>
#include <cstdint>

#define B   32
#define H   384
#define W   640
#define C   128
#define HS  96      // H / SCALE
#define WS  160     // W / SCALE
#define FW  30
#define THRESH 0.015f
#define TOPK 2000
#define PIX 4            // pixels per thread per select swath (4096 px/swath)
#define GRID 120         // persistent blocks (<= SM count, 1 block/SM -> co-resident)
#define NTHR 1024
#define PTS_PER_TASK 128
#define GTASKS (B * ((TOPK + PTS_PER_TASK - 1) / PTS_PER_TASK))   // 512 gather tasks

// Static device scratch (allocation-free rule: __device__ globals allowed)
__device__ float d_hwc[(size_t)B * HS * WS * C];   // transposed featmap (needed rows only)
__device__ int   d_idx[B * TOPK];                  // ascending selected linear indices, -1 invalid
__device__ int   d_count[B];                       // valid entries per batch
__device__ int          g_barCount[2];             // self-resetting arrival counters
__device__ unsigned     g_barSense[2];             // monotonically increasing senses

// ---------------------------------------------------------------------------
// Sense-reversing grid barrier. Safe across graph replays: count resets to 0
// by the last arriver; sense only ever increments. Requires all blocks
// co-resident (grid <= SMs at 1 block/SM).
// ---------------------------------------------------------------------------
__device__ __forceinline__ void grid_barrier(int idx)
{
    __threadfence();          // publish this thread's prior writes device-wide
    __syncthreads();
    if (threadIdx.x == 0) {
        unsigned s0 = atomicAdd(&g_barSense[idx], 0u);     // read current sense
        int my = atomicAdd(&g_barCount[idx], 1);
        if (my == GRID - 1) {
            g_barCount[idx] = 0;                            // reset for next replay
            __threadfence();
            atomicAdd(&g_barSense[idx], 1u);                // release
        } else {
            while (atomicAdd(&g_barSense[idx], 0u) == s0) { __nanosleep(64); }
        }
        __threadfence();      // acquire
    }
    __syncthreads();
}

// ---------------------------------------------------------------------------
// Single persistent kernel: select -> barrier -> sparse transpose -> barrier
// -> gather. 120 blocks x 1024 threads, all co-resident.
// ---------------------------------------------------------------------------
__global__ __launch_bounds__(NTHR) void fused_kernel(
    const float* __restrict__ prob,
    const float* __restrict__ feat,
    const float* __restrict__ ratio,
    const int* __restrict__ rshape_raw,
    float* __restrict__ pts_out,
    float* __restrict__ des_out)
{
    __shared__ __align__(16) char smemRaw[4 * 32 * 33 * sizeof(float)];  // 16.9 KB
    const int tid  = threadIdx.x;
    const int warp = tid >> 5;
    const int lane = tid & 31;

    // ======================= Phase A: ordered selection =======================
    if (blockIdx.x < B) {
        const int b = blockIdx.x;
        int* sWarpBase = (int*)smemRaw;         // [32]
        int* sTotal    = (int*)smemRaw + 32;

        // r_shape dtype sniff: int64 LE -> word 1 is high half of first value
        // (0, since H fits in 32 bits); int32 -> word 1 is W != 0.
        const int stride = (rshape_raw[1] == 0) ? 2 : 1;
        const int r0 = rshape_raw[(2 * b)     * stride];
        const int r1 = rshape_raw[(2 * b + 1) * stride];
        const int rowW     = r1 - 2 * FW;              // valid cols per row
        const int totalPix = (r0 - 2 * FW) * rowW;     // in-region pixel count
        const float rv = ratio[b];
        const float* pb = prob + (size_t)b * H * W;

        int base = 0;
        for (int sw = 0; sw < totalPix && base < TOPK; sw += NTHR * PIX) {
            const int pix0 = sw + PIX * tid;
            unsigned pmask = 0;
            int rr[PIX], cc[PIX];
            if (rowW > 0 && pix0 < totalPix) {
                const int rq = pix0 / rowW;
                int ri = FW + rq, ci = FW + pix0 - rq * rowW;
                #pragma unroll
                for (int j = 0; j < PIX; ++j) {
                    rr[j] = ri; cc[j] = ci;
                    if ((pix0 + j) < totalPix && pb[(size_t)ri * W + ci] > THRESH)
                        pmask |= (1u << j);
                    if (++ci >= FW + rowW) { ci = FW; ++ri; }
                }
            }
            const int cnt = __popc(pmask);

            // block exclusive scan
            int incl = cnt;
            #pragma unroll
            for (int d = 1; d < 32; d <<= 1) {
                int y = __shfl_up_sync(0xffffffffu, incl, d);
                if (lane >= d) incl += y;
            }
            if (lane == 31) sWarpBase[warp] = incl;
            __syncthreads();
            if (tid < 32) {
                int v = sWarpBase[tid];
                int x = v;
                #pragma unroll
                for (int d = 1; d < 32; d <<= 1) {
                    int y = __shfl_up_sync(0xffffffffu, x, d);
                    if (tid >= d) x += y;
                }
                sWarpBase[tid] = x - v;
                if (tid == 31) *sTotal = x;
            }
            __syncthreads();
            int pos = base + sWarpBase[warp] + (incl - cnt);

            #pragma unroll
            for (int j = 0; j < PIX; ++j) {
                if (pmask & (1u << j)) {
                    if (pos < TOPK) {
                        d_idx[b * TOPK + pos] = rr[j] * W + cc[j];
                        ((float2*)pts_out)[(size_t)b * TOPK + pos] =
                            make_float2((float)cc[j] / rv, (float)rr[j] / rv);
                    }
                    ++pos;
                }
            }
            const int total = *sTotal;
            __syncthreads();
            base += total;
        }

        const int cnt = (base < TOPK) ? base : TOPK;
        if (tid == 0) d_count[b] = cnt;
        for (int k = cnt + tid; k < TOPK; k += NTHR) {
            d_idx[b * TOPK + k] = -1;
            ((float2*)pts_out)[(size_t)b * TOPK + k] = make_float2(0.0f, 0.0f);
        }
    }

    grid_barrier(0);

    // =================== Phase B: sparse CHW -> HWC transpose ===================
    {
        __shared__ int sOff[B + 1];
        __shared__ int sYmin[B];
        float* tile = (float*)smemRaw;          // [4*32][33]

        // parallel per-batch row-range fetch, serial prefix by thread 0
        __shared__ int sN[B];
        if (tid < B) {
            const int cnt = d_count[tid];
            int ymin = 0, n = 0;
            if (cnt > 0) {
                const int rFirst = d_idx[tid * TOPK] / W;
                const int rLast  = d_idx[tid * TOPK + cnt - 1] / W;
                ymin = rFirst >> 2;
                int ymaxr = (rLast >> 2) + 1;
                if (ymaxr > HS - 1) ymaxr = HS - 1;
                n = ymaxr - ymin + 1;
            }
            sYmin[tid] = ymin;
            sN[tid] = n;
        }
        __syncthreads();
        if (tid == 0) {
            int acc = 0;
            #pragma unroll
            for (int b2 = 0; b2 < B; ++b2) { sOff[b2] = acc; acc += sN[b2]; }
            sOff[B] = acc;
        }
        __syncthreads();
        const int totalTasks = sOff[B] * 5;      // 5 x-tiles of 32 per row

        const int tx = tid & 31;        // x within tile (load) / c lane (store)
        const int cr = tid >> 5;        // channel row (load) / x row (store)

        for (int t = blockIdx.x; t < totalTasks; t += GRID) {
            const int rowTask = t / 5;
            const int xt = t - rowTask * 5;
            int b2 = 0;
            while (sOff[b2 + 1] <= rowTask) ++b2;       // uniform
            const int y = sYmin[b2] + (rowTask - sOff[b2]);

            const float* src = feat + ((size_t)b2 * C) * (HS * WS)
                                    + (size_t)y * WS + xt * 32;
            #pragma unroll
            for (int i = 0; i < 4; ++i) {
                const int c2 = i * 32 + cr;
                tile[(i * 32 + cr) * 33 + tx] = src[(size_t)c2 * (HS * WS) + tx];
            }
            __syncthreads();
            float* dst = d_hwc + ((size_t)(b2 * HS + y) * WS + xt * 32 + cr) * C;
            #pragma unroll
            for (int i = 0; i < 4; ++i) {
                dst[i * 32 + tx] = tile[(i * 32 + tx) * 33 + cr];
            }
            __syncthreads();
        }
    }

    grid_barrier(1);

    // ========================== Phase C: gather ==========================
    {
        int*    sOffP = (int*)smemRaw;                        // [128]
        float4* sWt   = (float4*)(smemRaw + 128 * sizeof(int) + 48); // aligned region
        sWt = (float4*)((((uintptr_t)sWt) + 15) & ~(uintptr_t)15);

        const int cg = tid & 31;     // channel group (4 ch)
        const int pl = tid >> 5;     // point lane 0..31
        const float4* hwc4 = (const float4*)d_hwc;

        for (int t = blockIdx.x; t < GTASKS; t += GRID) {
            const int b2 = t >> 4;                  // 16 tasks per batch
            const int p0 = (t & 15) * PTS_PER_TASK;

            __syncthreads();                        // protect smem reuse
            if (tid < PTS_PER_TASK) {
                const int p = p0 + tid;
                const int lin = (p < TOPK) ? d_idx[b2 * TOPK + p] : -1;
                int off = -1;
                float4 wt = make_float4(0.f, 0.f, 0.f, 0.f);
                if (lin >= 0) {
                    const int y = lin / W;
                    const int x = lin - y * W;
                    const int x0 = x >> 2;
                    const int y0 = y >> 2;
                    const float fx = (float)(x & 3) * 0.25f;
                    const float fy = (float)(y & 3) * 0.25f;
                    off = ((b2 * HS + y0) * WS + x0) * (C / 4);
                    wt = make_float4((1.f - fx) * (1.f - fy),   // Ia (y0,x0)
                                     (1.f - fx) * fy,           // Ib (y1,x0)
                                     fx * (1.f - fy),           // Ic (y0,x1)
                                     fx * fy);                  // Id (y1,x1)
                }
                sOffP[tid] = off;
                sWt[tid]   = wt;
            }
            __syncthreads();

            #pragma unroll
            for (int i = 0; i < 4; ++i) {
                const int j = pl + i * 32;
                const int p = p0 + j;
                if (p < TOPK) {
                    const int off = sOffP[j];
                    float4 v = make_float4(0.f, 0.f, 0.f, 0.f);
                    if (off >= 0) {
                        const float4 w = sWt[j];
                        const float4* basep = hwc4 + off + cg;
                        const float4 Ia = basep[0];
                        const float4 Ic = basep[C / 4];
                        const float4 Ib = basep[WS * (C / 4)];
                        const float4 Id = basep[WS * (C / 4) + C / 4];
                        v.x = Ia.x * w.x + Ib.x * w.y + Ic.x * w.z + Id.x * w.w;
                        v.y = Ia.y * w.x + Ib.y * w.y + Ic.y * w.z + Id.y * w.w;
                        v.z = Ia.z * w.x + Ib.z * w.y + Ic.z * w.z + Id.z * w.w;
                        v.w = Ia.w * w.x + Ib.w * w.y + Ic.w * w.z + Id.w * w.w;
                    }
                    ((float4*)des_out)[((size_t)b2 * TOPK + p) * (C / 4) + cg] = v;
                }
            }
        }
    }
}

// ---------------------------------------------------------------------------
extern "C" void kernel_launch(void* const* d_in, const int* in_sizes, int n_in,
                              void* d_out, int out_size)
{
    const float* prob   = (const float*)d_in[0];      // [B,1,H,W]
    const float* feat   = (const float*)d_in[1];      // [B,C,HS,WS]
    const float* ratio  = (const float*)d_in[2];      // [B,1]
    const int*   rshape = (const int*)d_in[3];        // [B,2] int32 (or int64-packed)

    float* pts_out = (float*)d_out;                        // [B,TOPK,2]
    float* des_out = (float*)d_out + (size_t)B * TOPK * 2; // [B,TOPK,C]

    fused_kernel<<<GRID, NTHR>>>(prob, feat, ratio, rshape, pts_out, des_out);
}

// round 9
// speedup vs baseline: 5.3819x; 1.3407x over previous
#include <cuda_runtime.h>
#include <cstdint>

#define B   32
#define H   384
#define W   640
#define C   128
#define HS  96      // H / SCALE
#define WS  160     // W / SCALE
#define FW  30
#define THRESH 0.015f
#define TOPK 2000
#define TBLOCKS 2048   // persistent transpose grid
#define PIX 4          // pixels per thread per swath in select

// Static device scratch (allocation-free rule: __device__ globals allowed)
__device__ float d_hwc[(size_t)B * HS * WS * C];   // transposed featmap (only needed rows valid)
__device__ int   d_idx[B * TOPK];                  // selected linear pixel indices, -1 = invalid
__device__ int   d_ymin[B];                        // first needed feat row per batch
__device__ int   d_nrows[B];                       // number of needed feat rows per batch

// ---------------------------------------------------------------------------
// Kernel 1: ordered selection, swath-parallel (proven R4 version).
// One block per batch; swaths of 1024*PIX pixels; one block scan per swath.
// ---------------------------------------------------------------------------
__global__ __launch_bounds__(1024) void select_kernel(
    const float* __restrict__ prob,
    const float* __restrict__ ratio,
    const int* __restrict__ rshape_raw,
    float* __restrict__ pts_out)
{
    const int b    = blockIdx.x;
    const int tid  = threadIdx.x;
    const int warp = tid >> 5;
    const int lane = tid & 31;

    __shared__ int sWarpBase[32];
    __shared__ int sTotal;
    __shared__ int sBase;
    __shared__ int sRmin, sRmax;
    if (tid == 0) { sBase = 0; sRmin = 0x7fffffff; sRmax = -1; }

    // r_shape dtype sniff: int64 LE -> word 1 is high half of first value (0);
    // int32 -> word 1 is W != 0.
    const int stride = (rshape_raw[1] == 0) ? 2 : 1;
    const int r0 = rshape_raw[(2 * b)     * stride];
    const int r1 = rshape_raw[(2 * b + 1) * stride];
    const int rowW     = r1 - 2 * FW;              // valid cols per row
    const int totalPix = (r0 - 2 * FW) * rowW;     // in-region pixel count
    const float rv = ratio[b];
    const float* pb = prob + (size_t)b * H * W;

    __syncthreads();

    for (int sw = 0; sw < totalPix; sw += 1024 * PIX) {
        const int pix0 = sw + PIX * tid;
        unsigned pmask = 0;
        int rr[PIX], cc[PIX];
        if (rowW > 0 && pix0 < totalPix) {
            const int rq = pix0 / rowW;
            int ri = FW + rq, ci = FW + pix0 - rq * rowW;
            #pragma unroll
            for (int j = 0; j < PIX; ++j) {
                rr[j] = ri; cc[j] = ci;
                if ((pix0 + j) < totalPix && pb[(size_t)ri * W + ci] > THRESH)
                    pmask |= (1u << j);
                if (++ci >= FW + rowW) { ci = FW; ++ri; }
            }
        }
        const int cnt = __popc(pmask);

        int incl = cnt;
        #pragma unroll
        for (int d = 1; d < 32; d <<= 1) {
            int y = __shfl_up_sync(0xffffffffu, incl, d);
            if (lane >= d) incl += y;
        }
        if (lane == 31) sWarpBase[warp] = incl;
        __syncthreads();
        if (tid < 32) {
            int v = sWarpBase[tid];
            int x = v;
            #pragma unroll
            for (int d = 1; d < 32; d <<= 1) {
                int y = __shfl_up_sync(0xffffffffu, x, d);
                if (tid >= d) x += y;
            }
            sWarpBase[tid] = x - v;
            if (tid == 31) sTotal = x;
        }
        __syncthreads();
        int pos = sBase + sWarpBase[warp] + (incl - cnt);

        int myRmin = 0x7fffffff, myRmax = -1;
        #pragma unroll
        for (int j = 0; j < PIX; ++j) {
            if (pmask & (1u << j)) {
                if (pos < TOPK) {
                    d_idx[b * TOPK + pos] = rr[j] * W + cc[j];
                    ((float2*)pts_out)[(size_t)b * TOPK + pos] =
                        make_float2((float)cc[j] / rv, (float)rr[j] / rv);
                    if (rr[j] < myRmin) myRmin = rr[j];
                    if (rr[j] > myRmax) myRmax = rr[j];
                }
                ++pos;
            }
        }
        if (myRmax >= 0) {
            atomicMin(&sRmin, myRmin);
            atomicMax(&sRmax, myRmax);
        }
        __syncthreads();
        if (tid == 0) sBase += sTotal;
        __syncthreads();
        if (sBase >= TOPK) break;
    }

    __syncthreads();
    {
        const int base = (sBase < TOPK) ? sBase : TOPK;
        for (int k = base + tid; k < TOPK; k += 1024) {
            d_idx[b * TOPK + k] = -1;
            ((float2*)pts_out)[(size_t)b * TOPK + k] = make_float2(0.0f, 0.0f);
        }
        if (tid == 0) {
            if (sRmax < 0) {
                d_ymin[b] = 0; d_nrows[b] = 0;
            } else {
                int ymin = sRmin >> 2;
                int ymax = (sRmax >> 2) + 1;
                if (ymax > HS - 1) ymax = HS - 1;
                d_ymin[b] = ymin;
                d_nrows[b] = ymax - ymin + 1;
            }
        }
    }
}

// ---------------------------------------------------------------------------
// Kernel 2: persistent CHW -> HWC transpose over a compact task list
// (proven R4 version). Task = (batch, feat row, tile); 20 tiles per row.
// ---------------------------------------------------------------------------
__global__ __launch_bounds__(256) void transpose_kernel(const float* __restrict__ feat)
{
    __shared__ int sOff[B + 1];
    __shared__ int sYmin[B];
    __shared__ float tile[32][33];

    const int t0 = threadIdx.y * 32 + threadIdx.x;
    if (t0 == 0) {
        int acc = 0;
        #pragma unroll
        for (int b = 0; b < B; ++b) {
            sOff[b] = acc;
            sYmin[b] = d_ymin[b];
            acc += d_nrows[b];
        }
        sOff[B] = acc;
    }
    __syncthreads();
    const int totalTasks = sOff[B] * 20;

    const int tx = threadIdx.x;  // 0..31
    const int ty = threadIdx.y;  // 0..7

    for (int t = blockIdx.x; t < totalTasks; t += TBLOCKS) {
        const int rowTask = t / 20;
        const int tileId  = t - rowTask * 20;
        int b = 0;
        while (sOff[b + 1] <= rowTask) ++b;        // uniform across block
        const int y  = sYmin[b] + (rowTask - sOff[b]);
        const int xt = tileId % 5;                 // 0..4 (x tiles of 32)
        const int ct = tileId / 5;                 // 0..3 (c tiles of 32)

        const float* src = feat + ((size_t)b * C) * (HS * WS) + (size_t)y * WS;
        #pragma unroll
        for (int i = 0; i < 4; ++i) {
            const int cc = ct * 32 + ty + i * 8;
            tile[ty + i * 8][tx] = src[(size_t)cc * (HS * WS) + xt * 32 + tx];
        }
        __syncthreads();
        float* dst = d_hwc + ((size_t)(b * HS + y) * WS) * C;
        #pragma unroll
        for (int i = 0; i < 4; ++i) {
            const int x = xt * 32 + ty + i * 8;
            dst[(size_t)x * C + ct * 32 + tx] = tile[tx][ty + i * 8];
        }
        __syncthreads();
    }
}

// ---------------------------------------------------------------------------
// Kernel 3: bilinear gather with tap-dedup.
// 256 threads = 8 warps x 32 channel-lanes; 64 points per block.
// Decode once into smem (tap offset + weights). Each warp walks 8
// CONSECUTIVE points serially, caching the 4 tap vectors in registers and
// reloading only when the coarse-cell offset changes (warp-uniform branch).
// Dense selections share cells between neighbors -> ~2-3 tap loads per 8
// points instead of 8.
// ---------------------------------------------------------------------------
__global__ __launch_bounds__(256) void gather_kernel(float* __restrict__ des_out)
{
    const int b  = blockIdx.y;
    const int p0 = blockIdx.x * 64;
    const int cg = threadIdx.x & 31;   // channel group (4 ch each, float4)
    const int wp = threadIdx.x >> 5;   // warp 0..7 -> points wp*8 .. wp*8+7

    __shared__ int    sOff[64];
    __shared__ float4 sWt[64];
    if (threadIdx.x < 64) {
        const int p = p0 + threadIdx.x;
        const int lin = (p < TOPK) ? d_idx[b * TOPK + p] : -1;
        int off = -1;
        float4 wt = make_float4(0.f, 0.f, 0.f, 0.f);
        if (lin >= 0) {
            const int y = lin / W;
            const int x = lin - y * W;
            const int x0 = x >> 2;
            const int y0 = y >> 2;
            const float fx = (float)(x & 3) * 0.25f;
            const float fy = (float)(y & 3) * 0.25f;
            off = ((b * HS + y0) * WS + x0) * (C / 4);
            wt = make_float4((1.f - fx) * (1.f - fy),   // Ia (y0,x0)
                             (1.f - fx) * fy,           // Ib (y1,x0)
                             fx * (1.f - fy),           // Ic (y0,x1)
                             fx * fy);                  // Id (y1,x1)
        }
        sOff[threadIdx.x] = off;
        sWt[threadIdx.x]  = wt;
    }
    __syncthreads();

    const float4* hwc4 = (const float4*)d_hwc;
    int cur = -1;
    float4 Ia = make_float4(0.f, 0.f, 0.f, 0.f), Ib = Ia, Ic = Ia, Id = Ia;

    const int jbase = wp * 8;
    #pragma unroll
    for (int i = 0; i < 8; ++i) {
        const int j = jbase + i;
        const int p = p0 + j;
        if (p >= TOPK) break;
        const int off = sOff[j];            // warp-uniform
        float4 v = make_float4(0.f, 0.f, 0.f, 0.f);
        if (off >= 0) {
            if (off != cur) {               // warp-uniform branch
                const float4* basep = hwc4 + off + cg;
                Ia = basep[0];                   // (y0,x0)
                Ic = basep[C / 4];               // (y0,x1)
                Ib = basep[WS * (C / 4)];        // (y1,x0)
                Id = basep[WS * (C / 4) + C / 4];// (y1,x1)
                cur = off;
            }
            const float4 w = sWt[j];
            v.x = Ia.x * w.x + Ib.x * w.y + Ic.x * w.z + Id.x * w.w;
            v.y = Ia.y * w.x + Ib.y * w.y + Ic.y * w.z + Id.y * w.w;
            v.z = Ia.z * w.x + Ib.z * w.y + Ic.z * w.z + Id.z * w.w;
            v.w = Ia.w * w.x + Ib.w * w.y + Ic.w * w.z + Id.w * w.w;
        }
        ((float4*)des_out)[((size_t)b * TOPK + p) * (C / 4) + cg] = v;
    }
}

// ---------------------------------------------------------------------------
extern "C" void kernel_launch(void* const* d_in, const int* in_sizes, int n_in,
                              void* d_out, int out_size)
{
    const float* prob   = (const float*)d_in[0];      // [B,1,H,W]
    const float* feat   = (const float*)d_in[1];      // [B,C,HS,WS]
    const float* ratio  = (const float*)d_in[2];      // [B,1]
    const int*   rshape = (const int*)d_in[3];        // [B,2] int32 (or int64-packed)

    float* pts_out = (float*)d_out;                        // [B,TOPK,2]
    float* des_out = (float*)d_out + (size_t)B * TOPK * 2; // [B,TOPK,C]

    select_kernel<<<B, 1024>>>(prob, ratio, rshape, pts_out);
    transpose_kernel<<<TBLOCKS, dim3(32, 8)>>>(feat);
    gather_kernel<<<dim3((TOPK + 63) / 64, B), 256>>>(des_out);
}